// round 1
// baseline (speedup 1.0000x reference)
#include <cuda_runtime.h>
#include <math.h>

#define NN    2048
#define EE    65536
#define SEQL  5
#define IND   32
#define HD    64
#define OUTD  16
#define EPSV  1e-5f

// ---------------- scratch (device globals; no allocation allowed) ----------------
__device__ float g_deg[NN];
__device__ int   g_cnt[NN];
__device__ int   g_rowptr[NN + 1];
__device__ int   g_fill[NN];
__device__ float g_dinv[NN];
__device__ float g_dself[NN];
__device__ int   g_csr_src[EE];
__device__ float g_csr_norm[EE];

__device__ float g_hwz[SEQL * NN * HD];
__device__ float g_hwh[SEQL * NN * HD];
__device__ float g_gz [SEQL * NN * HD];
__device__ float g_gh [SEQL * NN * HD];
__device__ float g_H  [NN * SEQL * HD];   // [n][t*64+k]
__device__ float g_emb[NN * HD];
__device__ float g_hw1[NN * HD];
__device__ float g_h1 [NN * HD];
__device__ float g_hw2[NN * HD];
__device__ float g_h2 [NN * HD];
__device__ float g_A  [NN * HD];
__device__ float g_B  [NN * HD];

// ---------------- setup kernels ----------------
__global__ void k_init() {
    int i = blockIdx.x * blockDim.x + threadIdx.x;
    if (i < NN) { g_deg[i] = 0.0f; g_cnt[i] = 0; }
}

__global__ void k_deg(const int* __restrict__ ei, const float* __restrict__ ew) {
    int e = blockIdx.x * blockDim.x + threadIdx.x;
    if (e < EE) {
        int dst = ei[EE + e];
        atomicAdd(&g_deg[dst], ew[e]);
        atomicAdd(&g_cnt[dst], 1);
    }
}

// single block of 1024 threads: exclusive scan of g_cnt[2048] -> rowptr, fill;
// also dinv/dself
__global__ void k_scan() {
    __shared__ int s[1024];
    int t = threadIdx.x;
    int a = g_cnt[2 * t];
    int b = g_cnt[2 * t + 1];
    int pairsum = a + b;
    s[t] = pairsum;
    for (int off = 1; off < 1024; off <<= 1) {
        __syncthreads();
        int v = (t >= off) ? s[t - off] : 0;
        __syncthreads();
        s[t] += v;
    }
    __syncthreads();
    int incl = s[t];
    int excl = incl - pairsum;
    g_rowptr[2 * t]     = excl;
    g_rowptr[2 * t + 1] = excl + a;
    g_fill[2 * t]       = excl;
    g_fill[2 * t + 1]   = excl + a;
    if (t == 1023) g_rowptr[NN] = incl;  // == EE

    for (int n = t; n < NN; n += 1024) {
        float d  = g_deg[n] + 1.0f;
        float di = rsqrtf(d);
        g_dinv[n]  = di;
        g_dself[n] = di * di;
    }
}

__global__ void k_scatter(const int* __restrict__ ei, const float* __restrict__ ew) {
    int e = blockIdx.x * blockDim.x + threadIdx.x;
    if (e < EE) {
        int src = ei[e];
        int dst = ei[EE + e];
        int pos = atomicAdd(&g_fill[dst], 1);
        g_csr_src[pos]  = src;
        g_csr_norm[pos] = g_dinv[src] * ew[e] * g_dinv[dst];
    }
}

// ---------------- TGCN timesteps (batched over all 5 t) ----------------
// hwz/hwh = x[t] @ Wcz / Wch   for all t at once (rows = SEQL*NN, K=32)
__global__ __launch_bounds__(256) void k_gemm_x(const float* __restrict__ x,
                                                const float* __restrict__ Wcz,
                                                const float* __restrict__ Wch) {
    int r = blockIdx.x * 4 + threadIdx.y;
    int k = threadIdx.x;
    const float* xr = x + r * IND;
    float az = 0.f, ah = 0.f;
#pragma unroll
    for (int i = 0; i < IND; i++) {
        float xv = xr[i];
        az = fmaf(xv, Wcz[i * HD + k], az);
        ah = fmaf(xv, Wch[i * HD + k], ah);
    }
    g_hwz[r * HD + k] = az;
    g_hwh[r * HD + k] = ah;
}

// graph aggregation for all (t,n): gz/gh = agg + dself*hw + bias
__global__ __launch_bounds__(64) void k_aggT(const float* __restrict__ bcz,
                                             const float* __restrict__ bch) {
    int blk = blockIdx.x;
    int t = blk >> 11;      // / NN
    int n = blk & (NN - 1);
    int k = threadIdx.x;
    const float* hz = g_hwz + t * NN * HD;
    const float* hh = g_hwh + t * NN * HD;
    int beg = g_rowptr[n], end = g_rowptr[n + 1];
    float sz = 0.f, sh = 0.f;
    for (int e = beg; e < end; e++) {
        int   s = g_csr_src[e];
        float w = g_csr_norm[e];
        sz = fmaf(w, hz[s * HD + k], sz);
        sh = fmaf(w, hh[s * HD + k], sh);
    }
    float ds = g_dself[n];
    int r = t * NN + n;
    g_gz[r * HD + k] = sz + ds * hz[n * HD + k] + bcz[k];
    g_gh[r * HD + k] = sh + ds * hh[n * HD + k] + bch[k];
}

// gate: Z=sigmoid(gz@Wlz[:64]+blz), Ht=tanh(gh@Wlh[:64]+blh), H=(1-Z)*Ht
__global__ __launch_bounds__(256) void k_gate(const float* __restrict__ Wlz,
                                              const float* __restrict__ blz,
                                              const float* __restrict__ Wlh,
                                              const float* __restrict__ blh) {
    int r = blockIdx.x * 4 + threadIdx.y;
    int k = threadIdx.x;
    const float* gz = g_gz + r * HD;
    const float* gh = g_gh + r * HD;
    float az = blz[k], ah = blh[k];
#pragma unroll 8
    for (int i = 0; i < HD; i++) {
        az = fmaf(gz[i], Wlz[i * HD + k], az);
        ah = fmaf(gh[i], Wlh[i * HD + k], ah);
    }
    float Z  = 1.0f / (1.0f + expf(-az));
    float Ht = tanhf(ah);
    int t = r >> 11;
    int n = r & (NN - 1);
    g_H[n * (SEQL * HD) + t * HD + k] = (1.0f - Z) * Ht;
}

// emb = H @ Wred + bred  (K=320, smem-tiled)
__global__ __launch_bounds__(256) void k_red(const float* __restrict__ Wred,
                                             const float* __restrict__ bred) {
    __shared__ float Ws[64 * 64];
    int r = blockIdx.x * 4 + threadIdx.y;
    int k = threadIdx.x;
    int tid = threadIdx.y * 64 + threadIdx.x;
    float acc = bred[k];
    for (int c = 0; c < SEQL * HD; c += 64) {
        for (int idx = tid; idx < 4096; idx += 256)
            Ws[idx] = Wred[(c + (idx >> 6)) * HD + (idx & 63)];
        __syncthreads();
        const float* Hr = g_H + r * (SEQL * HD) + c;
#pragma unroll 8
        for (int i = 0; i < 64; i++)
            acc = fmaf(Hr[i], Ws[i * HD + k], acc);
        __syncthreads();
    }
    g_emb[r * HD + k] = acc;
}

// hw = in @ W   (64x64)   which: 0 -> emb->hw1, 1 -> h1->hw2
__global__ __launch_bounds__(256) void k_gemm64(int which, const float* __restrict__ W) {
    const float* in = which ? g_h1 : g_emb;
    float*      out = which ? g_hw2 : g_hw1;
    int r = blockIdx.x * 4 + threadIdx.y;
    int k = threadIdx.x;
    const float* ir = in + r * HD;
    float a = 0.f;
#pragma unroll 8
    for (int i = 0; i < HD; i++)
        a = fmaf(ir[i], W[i * HD + k], a);
    out[r * HD + k] = a;
}

// GCN agg + bias + LayerNorm + relu.  which: 0 -> hw1->h1, 1 -> hw2->h2
__global__ __launch_bounds__(64) void k_aggln(int which,
                                              const float* __restrict__ bias,
                                              const float* __restrict__ gamma,
                                              const float* __restrict__ beta) {
    const float* hw = which ? g_hw2 : g_hw1;
    float*      out = which ? g_h2 : g_h1;
    int n = blockIdx.x;
    int k = threadIdx.x;
    int beg = g_rowptr[n], end = g_rowptr[n + 1];
    float sum = 0.f;
    for (int e = beg; e < end; e++) {
        int   s = g_csr_src[e];
        float w = g_csr_norm[e];
        sum = fmaf(w, hw[s * HD + k], sum);
    }
    float val = sum + g_dself[n] * hw[n * HD + k] + bias[k];

    __shared__ float sb[64];
    sb[k] = val;
    for (int off = 32; off > 0; off >>= 1) {
        __syncthreads();
        if (k < off) sb[k] += sb[k + off];
    }
    __syncthreads();
    float mu = sb[0] * (1.0f / 64.0f);
    __syncthreads();
    float d = val - mu;
    sb[k] = d * d;
    for (int off = 32; off > 0; off >>= 1) {
        __syncthreads();
        if (k < off) sb[k] += sb[k + off];
    }
    __syncthreads();
    float var = sb[0] * (1.0f / 64.0f);
    out[n * HD + k] = fmaxf(d * rsqrtf(var + EPSV) * gamma[k] + beta[k], 0.0f);
}

// node_pred = h2 @ Wout + bout  -> d_out[0 : 2048*16]
__global__ __launch_bounds__(256) void k_nodepred(const float* __restrict__ Wout,
                                                  const float* __restrict__ bout,
                                                  float* __restrict__ out) {
    int n = blockIdx.x * 16 + threadIdx.y;
    int o = threadIdx.x;
    const float* hr = g_h2 + n * HD;
    float a = bout[o];
#pragma unroll 8
    for (int i = 0; i < HD; i++)
        a = fmaf(hr[i], Wout[i * OUTD + o], a);
    out[n * OUTD + o] = a;
}

// A = emb @ Wi1[:64] + bi1 ;  B = emb @ Wi1[64:]
__global__ __launch_bounds__(256) void k_AB(const float* __restrict__ Wi1,
                                            const float* __restrict__ bi1) {
    int r = blockIdx.x * 4 + threadIdx.y;
    int k = threadIdx.x;
    const float* er = g_emb + r * HD;
    float a = bi1[k], b = 0.f;
#pragma unroll 8
    for (int i = 0; i < HD; i++) {
        float ev = er[i];
        a = fmaf(ev, Wi1[i * HD + k], a);
        b = fmaf(ev, Wi1[(HD + i) * HD + k], b);
    }
    g_A[r * HD + k] = a;
    g_B[r * HD + k] = b;
}

// scores[i][j] = sum_h relu(A[i][h]+B[j][h]) * Wi2[h] + bi2
// 64x64 tile per 256-thread block; 4x4 per thread; h-major smem (stride 68 for
// conflict-free, 16B-aligned float4 reads).
__global__ __launch_bounds__(256) void k_scores(const float* __restrict__ Wi2,
                                                const float* __restrict__ bi2,
                                                float* __restrict__ scores) {
    __shared__ __align__(16) float As[64 * 68];
    __shared__ __align__(16) float Bs[64 * 68];
    __shared__ float Ws[64];
    int tid = threadIdx.x;
    int tx = tid & 15, ty = tid >> 4;
    int i0 = blockIdx.y * 64, j0 = blockIdx.x * 64;

    for (int idx = tid; idx < 4096; idx += 256) {
        int h = idx & 63;     // consecutive tid -> consecutive h: coalesced GMEM
        int i = idx >> 6;
        As[h * 68 + i] = g_A[(i0 + i) * HD + h];
        Bs[h * 68 + i] = g_B[(j0 + i) * HD + h];
    }
    if (tid < 64) Ws[tid] = Wi2[tid];
    __syncthreads();

    float acc[4][4];
#pragma unroll
    for (int ii = 0; ii < 4; ii++)
#pragma unroll
        for (int jj = 0; jj < 4; jj++) acc[ii][jj] = 0.f;

    const float* ap = As + (ty << 2);
    const float* bp = Bs + (tx << 2);
#pragma unroll 4
    for (int h = 0; h < 64; h++) {
        float4 av = *reinterpret_cast<const float4*>(ap + h * 68);
        float4 bv = *reinterpret_cast<const float4*>(bp + h * 68);
        float w = Ws[h];
        float a[4] = {av.x, av.y, av.z, av.w};
        float b[4] = {bv.x, bv.y, bv.z, bv.w};
#pragma unroll
        for (int ii = 0; ii < 4; ii++)
#pragma unroll
            for (int jj = 0; jj < 4; jj++)
                acc[ii][jj] = fmaf(fmaxf(a[ii] + b[jj], 0.0f), w, acc[ii][jj]);
    }

    float b2 = bi2[0];
#pragma unroll
    for (int ii = 0; ii < 4; ii++) {
        int i = i0 + (ty << 2) + ii;
        float4 o = make_float4(acc[ii][0] + b2, acc[ii][1] + b2,
                               acc[ii][2] + b2, acc[ii][3] + b2);
        *reinterpret_cast<float4*>(&scores[i * NN + j0 + (tx << 2)]) = o;
    }
}

// ---------------- launch ----------------
extern "C" void kernel_launch(void* const* d_in, const int* in_sizes, int n_in,
                              void* d_out, int out_size) {
    (void)out_size;
    // Disambiguate input ordering: signature order has edge_index (2*E ints) at
    // slot 1; dict order has edge_weight (E floats) there and edge_index last.
    bool sig = (in_sizes[1] == 2 * EE);
    const float* x  = (const float*)d_in[0];
    const int*   ei = (const int*)(sig ? d_in[1] : d_in[n_in - 1]);
    const float* ew = (const float*)(sig ? d_in[2] : d_in[1]);
    int wo = sig ? 3 : 2;
    // order after edge args (identical in both layouts):
    // Wcz bcz Wlz blz Wcr bcr Wlr blr Wch bch Wlh blh Wred bred Wc1 bc1 Wc2 bc2
    // g1 be1 g2 be2 Wout bout Wi1 bi1 Wi2 bi2
    const float* Wcz  = (const float*)d_in[wo + 0];
    const float* bcz  = (const float*)d_in[wo + 1];
    const float* Wlz  = (const float*)d_in[wo + 2];
    const float* blz  = (const float*)d_in[wo + 3];
    const float* Wch  = (const float*)d_in[wo + 8];
    const float* bch  = (const float*)d_in[wo + 9];
    const float* Wlh  = (const float*)d_in[wo + 10];
    const float* blh  = (const float*)d_in[wo + 11];
    const float* Wred = (const float*)d_in[wo + 12];
    const float* bred = (const float*)d_in[wo + 13];
    const float* Wc1  = (const float*)d_in[wo + 14];
    const float* bc1  = (const float*)d_in[wo + 15];
    const float* Wc2  = (const float*)d_in[wo + 16];
    const float* bc2  = (const float*)d_in[wo + 17];
    const float* g1   = (const float*)d_in[wo + 18];
    const float* be1  = (const float*)d_in[wo + 19];
    const float* g2   = (const float*)d_in[wo + 20];
    const float* be2  = (const float*)d_in[wo + 21];
    const float* Wout = (const float*)d_in[wo + 22];
    const float* bout = (const float*)d_in[wo + 23];
    const float* Wi1  = (const float*)d_in[wo + 24];
    const float* bi1  = (const float*)d_in[wo + 25];
    const float* Wi2  = (const float*)d_in[wo + 26];
    const float* bi2  = (const float*)d_in[wo + 27];

    float* outp      = (float*)d_out;
    float* node_pred = outp;
    float* scores    = outp + NN * OUTD;

    // graph preprocessing (CSR by dst; avoids float atomics in the hot path)
    k_init<<<(NN + 255) / 256, 256>>>();
    k_deg<<<EE / 256, 256>>>(ei, ew);
    k_scan<<<1, 1024>>>();
    k_scatter<<<EE / 256, 256>>>(ei, ew);

    // TGCN timesteps, batched
    dim3 t64x4(64, 4);
    k_gemm_x<<<SEQL * NN / 4, t64x4>>>(x, Wcz, Wch);
    k_aggT<<<SEQL * NN, 64>>>(bcz, bch);
    k_gate<<<SEQL * NN / 4, t64x4>>>(Wlz, blz, Wlh, blh);

    // reduction + two GCN layers
    k_red<<<NN / 4, t64x4>>>(Wred, bred);
    k_gemm64<<<NN / 4, t64x4>>>(0, Wc1);
    k_aggln<<<NN, 64>>>(0, bc1, g1, be1);
    k_gemm64<<<NN / 4, t64x4>>>(1, Wc2);
    k_aggln<<<NN, 64>>>(1, bc2, g2, be2);
    k_nodepred<<<NN / 16, dim3(16, 16)>>>(Wout, bout, node_pred);

    // interaction predictor
    k_AB<<<NN / 4, t64x4>>>(Wi1, bi1);
    dim3 sgrid(NN / 64, NN / 64);
    k_scores<<<sgrid, 256>>>(Wi2, bi2, scores);
}

// round 2
// speedup vs baseline: 1.2021x; 1.2021x over previous
#include <cuda_runtime.h>
#include <math.h>

#define NN    2048
#define EE    65536
#define SEQL  5
#define IND   32
#define HD    64
#define OUTD  16
#define EPSV  1e-5f

// ---------------- scratch (device globals; no allocation allowed) ----------------
__device__ float  g_deg[NN];
__device__ int    g_cnt[NN];
__device__ int    g_rowptr[NN + 1];
__device__ int    g_fill[NN];
__device__ float  g_dinv[NN];
__device__ float  g_dself[NN];
__device__ float2 g_csr[EE];          // (src as int bits, norm)

__device__ float  g_Wzl[IND * HD];    // Wcz @ Wlz[:HD]
__device__ float  g_Whl[IND * HD];    // Wch @ Wlh[:HD]
__device__ float  g_biasz[HD];        // bcz @ Wlz[:HD] + blz
__device__ float  g_biash[HD];

__device__ float2 g_hw[SEQL * NN * HD];   // (z,h) pre-aggregation features
__device__ float  g_H  [NN * SEQL * HD];  // [n][t*64+k]
__device__ float  g_hw1[NN * HD];
__device__ float  g_hw2[NN * HD];
__device__ float  g_A  [NN * HD];
__device__ float  g_B  [NN * HD];

// ---------------- setup kernels ----------------
__global__ void k_init() {
    int i = blockIdx.x * blockDim.x + threadIdx.x;
    if (i < NN) { g_deg[i] = 0.0f; g_cnt[i] = 0; }
}

__global__ void k_deg(const int* __restrict__ ei, const float* __restrict__ ew) {
    int e = blockIdx.x * blockDim.x + threadIdx.x;
    if (e < EE) {
        int dst = ei[EE + e];
        atomicAdd(&g_deg[dst], ew[e]);
        atomicAdd(&g_cnt[dst], 1);
    }
}

// single block of 1024 threads: exclusive scan of g_cnt[2048] -> rowptr, fill; dinv/dself
__global__ void k_scan() {
    __shared__ int s[1024];
    int t = threadIdx.x;
    int a = g_cnt[2 * t];
    int b = g_cnt[2 * t + 1];
    int pairsum = a + b;
    s[t] = pairsum;
    for (int off = 1; off < 1024; off <<= 1) {
        __syncthreads();
        int v = (t >= off) ? s[t - off] : 0;
        __syncthreads();
        s[t] += v;
    }
    __syncthreads();
    int incl = s[t];
    int excl = incl - pairsum;
    g_rowptr[2 * t]     = excl;
    g_rowptr[2 * t + 1] = excl + a;
    g_fill[2 * t]       = excl;
    g_fill[2 * t + 1]   = excl + a;
    if (t == 1023) g_rowptr[NN] = incl;

    for (int n = t; n < NN; n += 1024) {
        float d  = g_deg[n] + 1.0f;
        float di = rsqrtf(d);
        g_dinv[n]  = di;
        g_dself[n] = di * di;
    }
}

__global__ void k_scatter(const int* __restrict__ ei, const float* __restrict__ ew) {
    int e = blockIdx.x * blockDim.x + threadIdx.x;
    if (e < EE) {
        int src = ei[e];
        int dst = ei[EE + e];
        int pos = atomicAdd(&g_fill[dst], 1);
        g_csr[pos] = make_float2(__int_as_float(src), g_dinv[src] * ew[e] * g_dinv[dst]);
    }
}

// combined weights: Wzl = Wcz @ Wlz[:64]; biasz = bcz @ Wlz[:64] + blz (ditto h)
__global__ __launch_bounds__(256) void k_wcomb(
    const float* __restrict__ Wcz, const float* __restrict__ bcz,
    const float* __restrict__ Wlz, const float* __restrict__ blz,
    const float* __restrict__ Wch, const float* __restrict__ bch,
    const float* __restrict__ Wlh, const float* __restrict__ blh) {
    bool z = (blockIdx.x == 0);
    const float* Wc = z ? Wcz : Wch;
    const float* Wl = z ? Wlz : Wlh;
    const float* bc = z ? bcz : bch;
    const float* bl = z ? blz : blh;
    float* Wo = z ? g_Wzl : g_Whl;
    float* bo = z ? g_biasz : g_biash;
    int tid = threadIdx.x;
#pragma unroll
    for (int q = 0; q < 8; q++) {
        int o = tid + 256 * q;          // o < 2048
        int i = o >> 6, k = o & 63;
        float acc = 0.f;
#pragma unroll 8
        for (int m = 0; m < HD; m++)
            acc = fmaf(Wc[i * HD + m], Wl[m * HD + k], acc);
        Wo[o] = acc;
    }
    if (tid < HD) {
        float acc = bl[tid];
#pragma unroll 8
        for (int m = 0; m < HD; m++)
            acc = fmaf(bc[m], Wl[m * HD + tid], acc);
        bo[tid] = acc;
    }
}

// hw(z,h) = x[t] @ Wzl / Whl   for all t (rows = SEQL*NN, K=32)
__global__ __launch_bounds__(256) void k_gemm_x(const float* __restrict__ x) {
    int r = blockIdx.x * 4 + threadIdx.y;
    int k = threadIdx.x;
    const float* xr = x + r * IND;
    float az = 0.f, ah = 0.f;
#pragma unroll
    for (int i = 0; i < IND; i++) {
        float xv = xr[i];
        az = fmaf(xv, g_Wzl[i * HD + k], az);
        ah = fmaf(xv, g_Whl[i * HD + k], ah);
    }
    g_hw[r * HD + k] = make_float2(az, ah);
}

// aggregation + gates fused: H[n][t*64+k] = (1-sigmoid(aggz)) * tanh(aggh)
__global__ __launch_bounds__(64) void k_aggHT() {
    int blk = blockIdx.x;
    int t = blk >> 11;
    int n = blk & (NN - 1);
    int k = threadIdx.x;
    const float2* hw = g_hw + t * NN * HD;
    int beg = g_rowptr[n], end = g_rowptr[n + 1];
    float sz = 0.f, sh = 0.f;
    for (int e = beg; e < end; e++) {
        float2 cw = g_csr[e];
        int    s  = __float_as_int(cw.x);
        float2 v  = hw[s * HD + k];
        sz = fmaf(cw.y, v.x, sz);
        sh = fmaf(cw.y, v.y, sh);
    }
    float  ds   = g_dself[n];
    float2 self = hw[n * HD + k];
    float  za = sz + ds * self.x + g_biasz[k];
    float  ha = sh + ds * self.y + g_biash[k];
    float  Z  = 1.0f / (1.0f + expf(-za));
    float  Ht = tanhf(ha);
    g_H[n * (SEQL * HD) + t * HD + k] = (1.0f - Z) * Ht;
}

// emb = H @ Wred + bred; then hw1 = emb@Wc1; A = emb@Wi1[:64]+bi1; B = emb@Wi1[64:]
__global__ __launch_bounds__(256) void k_red_plus(
    const float* __restrict__ Wred, const float* __restrict__ bred,
    const float* __restrict__ Wc1,
    const float* __restrict__ Wi1,  const float* __restrict__ bi1) {
    __shared__ float es[4][HD];
    int r = blockIdx.x * 4 + threadIdx.y;
    int k = threadIdx.x;
    const float* Hr = g_H + r * (SEQL * HD);
    float acc = bred[k];
#pragma unroll 8
    for (int i = 0; i < SEQL * HD; i++)
        acc = fmaf(Hr[i], Wred[i * HD + k], acc);
    es[threadIdx.y][k] = acc;
    __syncthreads();
    float h1 = 0.f, a = bi1[k], b = 0.f;
#pragma unroll 8
    for (int i = 0; i < HD; i++) {
        float ev = es[threadIdx.y][i];
        h1 = fmaf(ev, Wc1[i * HD + k], h1);
        a  = fmaf(ev, Wi1[i * HD + k], a);
        b  = fmaf(ev, Wi1[(HD + i) * HD + k], b);
    }
    g_hw1[r * HD + k] = h1;
    g_A  [r * HD + k] = a;
    g_B  [r * HD + k] = b;
}

// GCN agg(hw1)+bias -> LN -> relu -> h1; then hw2 = h1 @ Wc2
__global__ __launch_bounds__(64) void k_agg1(
    const float* __restrict__ bc1, const float* __restrict__ g1,
    const float* __restrict__ be1, const float* __restrict__ Wc2) {
    int n = blockIdx.x;
    int k = threadIdx.x;
    int beg = g_rowptr[n], end = g_rowptr[n + 1];
    float sum = 0.f;
    for (int e = beg; e < end; e++) {
        float2 cw = g_csr[e];
        int    s  = __float_as_int(cw.x);
        sum = fmaf(cw.y, g_hw1[s * HD + k], sum);
    }
    float val = sum + g_dself[n] * g_hw1[n * HD + k] + bc1[k];

    __shared__ float sb[HD];
    __shared__ float sh[HD];
    sb[k] = val;
    for (int off = 32; off > 0; off >>= 1) {
        __syncthreads();
        if (k < off) sb[k] += sb[k + off];
    }
    __syncthreads();
    float mu = sb[0] * (1.0f / 64.0f);
    __syncthreads();
    float d = val - mu;
    sb[k] = d * d;
    for (int off = 32; off > 0; off >>= 1) {
        __syncthreads();
        if (k < off) sb[k] += sb[k + off];
    }
    __syncthreads();
    float var = sb[0] * (1.0f / 64.0f);
    float h = fmaxf(d * rsqrtf(var + EPSV) * g1[k] + be1[k], 0.0f);
    sh[k] = h;
    __syncthreads();
    float o = 0.f;
#pragma unroll 8
    for (int i = 0; i < HD; i++)
        o = fmaf(sh[i], Wc2[i * HD + k], o);
    g_hw2[n * HD + k] = o;
}

// GCN agg(hw2)+bias -> LN -> relu -> h2; then node_pred = h2 @ Wout + bout
__global__ __launch_bounds__(64) void k_agg2(
    const float* __restrict__ bc2, const float* __restrict__ g2,
    const float* __restrict__ be2, const float* __restrict__ Wout,
    const float* __restrict__ bout, float* __restrict__ node_pred) {
    int n = blockIdx.x;
    int k = threadIdx.x;
    int beg = g_rowptr[n], end = g_rowptr[n + 1];
    float sum = 0.f;
    for (int e = beg; e < end; e++) {
        float2 cw = g_csr[e];
        int    s  = __float_as_int(cw.x);
        sum = fmaf(cw.y, g_hw2[s * HD + k], sum);
    }
    float val = sum + g_dself[n] * g_hw2[n * HD + k] + bc2[k];

    __shared__ float sb[HD];
    __shared__ float sh[HD];
    sb[k] = val;
    for (int off = 32; off > 0; off >>= 1) {
        __syncthreads();
        if (k < off) sb[k] += sb[k + off];
    }
    __syncthreads();
    float mu = sb[0] * (1.0f / 64.0f);
    __syncthreads();
    float d = val - mu;
    sb[k] = d * d;
    for (int off = 32; off > 0; off >>= 1) {
        __syncthreads();
        if (k < off) sb[k] += sb[k + off];
    }
    __syncthreads();
    float var = sb[0] * (1.0f / 64.0f);
    sh[k] = fmaxf(d * rsqrtf(var + EPSV) * g2[k] + be2[k], 0.0f);
    __syncthreads();
    if (k < OUTD) {
        float o = bout[k];
#pragma unroll 8
        for (int i = 0; i < HD; i++)
            o = fmaf(sh[i], Wout[i * OUTD + k], o);
        node_pred[n * OUTD + k] = o;
    }
}

// ---------------- scores with packed f32x2 ----------------
__device__ __forceinline__ void lds2(unsigned long long& x, unsigned long long& y,
                                     const float* p) {
    unsigned a = (unsigned)__cvta_generic_to_shared(p);
    asm volatile("ld.shared.v2.b64 {%0, %1}, [%2];" : "=l"(x), "=l"(y) : "r"(a));
}

__device__ __forceinline__ void rfma(unsigned long long& acc, unsigned long long a,
                                     unsigned long long b, unsigned long long w) {
    unsigned long long t, m;
    float lo, hi;
    asm("add.rn.f32x2 %0, %1, %2;" : "=l"(t) : "l"(a), "l"(b));
    asm("mov.b64 {%0, %1}, %2;" : "=f"(lo), "=f"(hi) : "l"(t));
    lo = fmaxf(lo, 0.0f);
    hi = fmaxf(hi, 0.0f);
    asm("mov.b64 %0, {%1, %2};" : "=l"(m) : "f"(lo), "f"(hi));
    asm("fma.rn.f32x2 %0, %1, %2, %3;" : "=l"(acc) : "l"(m), "l"(w), "l"(acc));
}

// scores[i][j] = sum_h relu(A[i][h]+B[j][h]) * Wi2[h] + bi2
// 64x64 tile per 256-thread block; smem [i][h] layout (stride 68 floats, rows 16B-aligned);
// h processed 4 at a time as two f32x2 pairs; i = ii*16+ty, j = jj*16+tx.
__global__ __launch_bounds__(256) void k_scores(const float* __restrict__ Wi2,
                                                const float* __restrict__ bi2,
                                                float* __restrict__ scores) {
    __shared__ __align__(16) float As[64 * 68];
    __shared__ __align__(16) float Bs[64 * 68];
    __shared__ __align__(16) float Ws[64];
    int tid = threadIdx.x;
    int tx = tid & 15, ty = tid >> 4;
    int i0 = blockIdx.y * 64, j0 = blockIdx.x * 64;

    for (int idx = tid; idx < 4096; idx += 256) {
        int i = idx >> 6, h = idx & 63;
        As[i * 68 + h] = g_A[(i0 + i) * HD + h];
        Bs[i * 68 + h] = g_B[(j0 + i) * HD + h];
    }
    if (tid < 64) Ws[tid] = Wi2[tid];
    __syncthreads();

    unsigned long long acc[4][4];
#pragma unroll
    for (int ii = 0; ii < 4; ii++)
#pragma unroll
        for (int jj = 0; jj < 4; jj++) acc[ii][jj] = 0ull;

    const float* ap = As + ty * 68;
    const float* bp = Bs + tx * 68;
#pragma unroll 2
    for (int h = 0; h < 64; h += 4) {
        unsigned long long a0[4], a1[4], b0[4], b1[4], w0, w1;
        lds2(w0, w1, Ws + h);
#pragma unroll
        for (int ii = 0; ii < 4; ii++)
            lds2(a0[ii], a1[ii], ap + ii * (16 * 68) + h);
#pragma unroll
        for (int jj = 0; jj < 4; jj++)
            lds2(b0[jj], b1[jj], bp + jj * (16 * 68) + h);
#pragma unroll
        for (int ii = 0; ii < 4; ii++)
#pragma unroll
            for (int jj = 0; jj < 4; jj++) {
                rfma(acc[ii][jj], a0[ii], b0[jj], w0);
                rfma(acc[ii][jj], a1[ii], b1[jj], w1);
            }
    }

    float b2 = bi2[0];
#pragma unroll
    for (int ii = 0; ii < 4; ii++) {
#pragma unroll
        for (int jj = 0; jj < 4; jj++) {
            float lo, hi;
            asm("mov.b64 {%0, %1}, %2;" : "=f"(lo), "=f"(hi) : "l"(acc[ii][jj]));
            int i = i0 + ii * 16 + ty;
            int j = j0 + jj * 16 + tx;
            scores[i * NN + j] = lo + hi + b2;
        }
    }
}

// ---------------- launch ----------------
extern "C" void kernel_launch(void* const* d_in, const int* in_sizes, int n_in,
                              void* d_out, int out_size) {
    (void)out_size;
    bool sig = (in_sizes[1] == 2 * EE);
    const float* x  = (const float*)d_in[0];
    const int*   ei = (const int*)(sig ? d_in[1] : d_in[n_in - 1]);
    const float* ew = (const float*)(sig ? d_in[2] : d_in[1]);
    int wo = sig ? 3 : 2;
    const float* Wcz  = (const float*)d_in[wo + 0];
    const float* bcz  = (const float*)d_in[wo + 1];
    const float* Wlz  = (const float*)d_in[wo + 2];
    const float* blz  = (const float*)d_in[wo + 3];
    const float* Wch  = (const float*)d_in[wo + 8];
    const float* bch  = (const float*)d_in[wo + 9];
    const float* Wlh  = (const float*)d_in[wo + 10];
    const float* blh  = (const float*)d_in[wo + 11];
    const float* Wred = (const float*)d_in[wo + 12];
    const float* bred = (const float*)d_in[wo + 13];
    const float* Wc1  = (const float*)d_in[wo + 14];
    const float* bc1  = (const float*)d_in[wo + 15];
    const float* Wc2  = (const float*)d_in[wo + 16];
    const float* bc2  = (const float*)d_in[wo + 17];
    const float* g1   = (const float*)d_in[wo + 18];
    const float* be1  = (const float*)d_in[wo + 19];
    const float* g2   = (const float*)d_in[wo + 20];
    const float* be2  = (const float*)d_in[wo + 21];
    const float* Wout = (const float*)d_in[wo + 22];
    const float* bout = (const float*)d_in[wo + 23];
    const float* Wi1  = (const float*)d_in[wo + 24];
    const float* bi1  = (const float*)d_in[wo + 25];
    const float* Wi2  = (const float*)d_in[wo + 26];
    const float* bi2  = (const float*)d_in[wo + 27];

    float* outp      = (float*)d_out;
    float* node_pred = outp;
    float* scores    = outp + NN * OUTD;

    // graph preprocessing (CSR by dst)
    k_init<<<(NN + 255) / 256, 256>>>();
    k_deg<<<EE / 256, 256>>>(ei, ew);
    k_scan<<<1, 1024>>>();
    k_scatter<<<EE / 256, 256>>>(ei, ew);

    // combined gate weights, then TGCN timesteps batched
    k_wcomb<<<2, 256>>>(Wcz, bcz, Wlz, blz, Wch, bch, Wlh, blh);
    dim3 t64x4(64, 4);
    k_gemm_x<<<SEQL * NN / 4, t64x4>>>(x);
    k_aggHT<<<SEQL * NN, 64>>>();

    // reduction + interaction inputs + two GCN layers (fused)
    k_red_plus<<<NN / 4, t64x4>>>(Wred, bred, Wc1, Wi1, bi1);
    k_agg1<<<NN, 64>>>(bc1, g1, be1, Wc2);
    k_agg2<<<NN, 64>>>(bc2, g2, be2, Wout, bout, node_pred);

    // interaction predictor
    dim3 sgrid(NN / 64, NN / 64);
    k_scores<<<sgrid, 256>>>(Wi2, bi2, scores);
}

// round 3
// speedup vs baseline: 1.2031x; 1.0008x over previous
#include <cuda_runtime.h>
#include <math.h>

#define NN    2048
#define EE    65536
#define SEQL  5
#define IND   32
#define HD    64
#define OUTD  16
#define EPSV  1e-5f

// ---------------- scratch (device globals) ----------------
__device__ unsigned long long g_pk[NN];   // packed: cnt<<44 | fixed20(sum w)
__device__ int    g_rank[EE];
__device__ int    g_rowptr[NN + 1];
__device__ float  g_dinv[NN];
__device__ float  g_dself[NN];
__device__ float2 g_csr[EE];              // (src as int bits, norm)

__device__ float  g_Wzl[IND * HD];        // Wcz @ Wlz[:HD]
__device__ float  g_Whl[IND * HD];        // Wch @ Wlh[:HD]
__device__ float  g_biasz[HD];
__device__ float  g_biash[HD];

__device__ float2 g_hw[SEQL * NN * HD];   // [t][n][k] (z,h)
__device__ float  g_H  [NN * SEQL * HD];  // [n][t*64+k]
__device__ float  g_hw1[NN * HD];
__device__ float  g_hw2[NN * HD];
__device__ float  g_A  [NN * HD];
__device__ float  g_B  [NN * HD];

// ---------------- K1: combined gate weights + zero packed counters ----------------
__global__ __launch_bounds__(256) void k_pre(
    const float* __restrict__ Wcz, const float* __restrict__ bcz,
    const float* __restrict__ Wlz, const float* __restrict__ blz,
    const float* __restrict__ Wch, const float* __restrict__ bch,
    const float* __restrict__ Wlh, const float* __restrict__ blh) {
    int b = blockIdx.x;
    int tid = threadIdx.x;
    if (b >= 2) {                     // blocks 2..9 zero g_pk
        g_pk[(b - 2) * 256 + tid] = 0ull;
        return;
    }
    bool z = (b == 0);
    const float* Wc = z ? Wcz : Wch;
    const float* Wl = z ? Wlz : Wlh;
    const float* bc = z ? bcz : bch;
    const float* bl = z ? blz : blh;
    float* Wo = z ? g_Wzl : g_Whl;
    float* bo = z ? g_biasz : g_biash;
#pragma unroll
    for (int q = 0; q < 8; q++) {
        int o = tid + 256 * q;        // o < 2048
        int i = o >> 6, k = o & 63;
        float acc = 0.f;
#pragma unroll 8
        for (int m = 0; m < HD; m++)
            acc = fmaf(Wc[i * HD + m], Wl[m * HD + k], acc);
        Wo[o] = acc;
    }
    if (tid < HD) {
        float acc = bl[tid];
#pragma unroll 8
        for (int m = 0; m < HD; m++)
            acc = fmaf(bc[m], Wl[m * HD + tid], acc);
        bo[tid] = acc;
    }
}

// ---------------- K2: degree + per-edge rank via single packed atomic ----------------
__global__ void k_deg(const int* __restrict__ ei, const float* __restrict__ ew) {
    int e = blockIdx.x * blockDim.x + threadIdx.x;
    if (e < EE) {
        int dst = ei[EE + e];
        unsigned fixw = __float2uint_rn(ew[e] * 1048576.0f);   // w in [0,1)
        unsigned long long pk = (1ull << 44) | (unsigned long long)fixw;
        unsigned long long old = atomicAdd(&g_pk[dst], pk);
        g_rank[e] = (int)(old >> 44);
    }
}

// ---------------- K3: scan counts -> rowptr; deg -> dinv/dself ----------------
__global__ void k_scan() {
    __shared__ int s[1024];
    int t = threadIdx.x;
    unsigned long long p0 = g_pk[2 * t];
    unsigned long long p1 = g_pk[2 * t + 1];
    int a = (int)(p0 >> 44);
    int b = (int)(p1 >> 44);
    int pairsum = a + b;
    s[t] = pairsum;
    for (int off = 1; off < 1024; off <<= 1) {
        __syncthreads();
        int v = (t >= off) ? s[t - off] : 0;
        __syncthreads();
        s[t] += v;
    }
    __syncthreads();
    int incl = s[t];
    int excl = incl - pairsum;
    g_rowptr[2 * t]     = excl;
    g_rowptr[2 * t + 1] = excl + a;
    if (t == 1023) g_rowptr[NN] = incl;

    const float inv20 = 1.0f / 1048576.0f;
    const unsigned long long mask = (1ull << 44) - 1;
    {
        float d0 = (float)(double)(p0 & mask) * inv20 + 1.0f;
        float d1 = (float)(double)(p1 & mask) * inv20 + 1.0f;
        float i0 = rsqrtf(d0), i1 = rsqrtf(d1);
        g_dinv[2 * t] = i0;      g_dself[2 * t] = i0 * i0;
        g_dinv[2 * t + 1] = i1;  g_dself[2 * t + 1] = i1 * i1;
    }
}

// ---------------- K4: scatter (atomic-free) + gemm_x, block-range split ----------------
__global__ __launch_bounds__(256) void k_sc_gx(const int* __restrict__ ei,
                                               const float* __restrict__ ew,
                                               const float* __restrict__ x) {
    int b = blockIdx.x;
    int tid = threadIdx.x;
    if (b < 256) {                        // scatter: position known, no atomics
        int e = b * 256 + tid;
        int src = ei[e];
        int dst = ei[EE + e];
        int pos = g_rowptr[dst] + g_rank[e];
        g_csr[pos] = make_float2(__int_as_float(src),
                                 g_dinv[src] * ew[e] * g_dinv[dst]);
        return;
    }
    // gemm_x: hw(z,h) = x[t] @ Wzl/Whl, rows = SEQL*NN, K=32
    int r = (b - 256) * 4 + (tid >> 6);
    int k = tid & 63;
    const float* xr = x + r * IND;
    float az = 0.f, ah = 0.f;
#pragma unroll
    for (int i = 0; i < IND; i++) {
        float xv = xr[i];
        az = fmaf(xv, g_Wzl[i * HD + k], az);
        ah = fmaf(xv, g_Whl[i * HD + k], ah);
    }
    g_hw[r * HD + k] = make_float2(az, ah);
}

// ---------------- K5: aggregation + gates, all 5 timesteps, 4 nodes/block ----------------
__global__ __launch_bounds__(256) void k_aggHT() {
    int n = blockIdx.x * 4 + (threadIdx.x >> 6);
    int k = threadIdx.x & 63;
    int beg = g_rowptr[n], end = g_rowptr[n + 1];
    float sz0 = 0.f, sh0 = 0.f, sz1 = 0.f, sh1 = 0.f, sz2 = 0.f, sh2 = 0.f;
    float sz3 = 0.f, sh3 = 0.f, sz4 = 0.f, sh4 = 0.f;
    for (int e = beg; e < end; e++) {
        float2 cw = g_csr[e];
        int    s  = __float_as_int(cw.x);
        float  w  = cw.y;
        int base = s * HD + k;
        float2 v0 = g_hw[base];
        float2 v1 = g_hw[1 * NN * HD + base];
        float2 v2 = g_hw[2 * NN * HD + base];
        float2 v3 = g_hw[3 * NN * HD + base];
        float2 v4 = g_hw[4 * NN * HD + base];
        sz0 = fmaf(w, v0.x, sz0); sh0 = fmaf(w, v0.y, sh0);
        sz1 = fmaf(w, v1.x, sz1); sh1 = fmaf(w, v1.y, sh1);
        sz2 = fmaf(w, v2.x, sz2); sh2 = fmaf(w, v2.y, sh2);
        sz3 = fmaf(w, v3.x, sz3); sh3 = fmaf(w, v3.y, sh3);
        sz4 = fmaf(w, v4.x, sz4); sh4 = fmaf(w, v4.y, sh4);
    }
    float ds = g_dself[n];
    float bz = g_biasz[k], bh = g_biash[k];
    int base = n * HD + k;
    float* Hn = g_H + n * (SEQL * HD) + k;
#pragma unroll
    for (int t = 0; t < SEQL; t++) {
        float2 self = g_hw[t * NN * HD + base];
        float sz, sh;
        switch (t) {
            case 0: sz = sz0; sh = sh0; break;
            case 1: sz = sz1; sh = sh1; break;
            case 2: sz = sz2; sh = sh2; break;
            case 3: sz = sz3; sh = sh3; break;
            default: sz = sz4; sh = sh4; break;
        }
        float za = sz + ds * self.x + bz;
        float ha = sh + ds * self.y + bh;
        float Z  = 1.0f / (1.0f + expf(-za));
        float Ht = tanhf(ha);
        Hn[t * HD] = (1.0f - Z) * Ht;
    }
}

// ---------------- K6: emb = H@Wred+bred; hw1 = emb@Wc1; A/B = emb@Wi1 ----------------
__global__ __launch_bounds__(512) void k_red_plus(
    const float* __restrict__ Wred, const float* __restrict__ bred,
    const float* __restrict__ Wc1,
    const float* __restrict__ Wi1,  const float* __restrict__ bi1) {
    __shared__ float es[8][HD];
    int g = threadIdx.x >> 6;
    int r = blockIdx.x * 8 + g;
    int k = threadIdx.x & 63;
    const float* Hr = g_H + r * (SEQL * HD);
    float acc = bred[k];
#pragma unroll 8
    for (int i = 0; i < SEQL * HD; i++)
        acc = fmaf(Hr[i], Wred[i * HD + k], acc);
    es[g][k] = acc;
    __syncthreads();
    float h1 = 0.f, a = bi1[k], b = 0.f;
#pragma unroll 8
    for (int i = 0; i < HD; i++) {
        float ev = es[g][i];
        h1 = fmaf(ev, Wc1[i * HD + k], h1);
        a  = fmaf(ev, Wi1[i * HD + k], a);
        b  = fmaf(ev, Wi1[(HD + i) * HD + k], b);
    }
    g_hw1[r * HD + k] = h1;
    g_A  [r * HD + k] = a;
    g_B  [r * HD + k] = b;
}

// group-of-64 sum helper: warp reduce + 2-warp combine via smem slot
__device__ __forceinline__ float gsum64(float v, float* slots, int g, int tid) {
#pragma unroll
    for (int off = 16; off > 0; off >>= 1)
        v += __shfl_xor_sync(0xffffffffu, v, off);
    if ((tid & 31) == 0) slots[tid >> 5] = v;
    __syncthreads();
    return slots[g * 2] + slots[g * 2 + 1];
}

// ---------------- K7: agg(hw1)+LN+relu -> smem; hw2 = h1@Wc2; 4 nodes/block ----------------
__global__ __launch_bounds__(256) void k_agg1(
    const float* __restrict__ bc1, const float* __restrict__ g1,
    const float* __restrict__ be1, const float* __restrict__ Wc2) {
    __shared__ float s1[8], s2[8];
    __shared__ float sh[4][HD];
    int tid = threadIdx.x;
    int g = tid >> 6;
    int n = blockIdx.x * 4 + g;
    int k = tid & 63;
    int beg = g_rowptr[n], end = g_rowptr[n + 1];
    float sum = 0.f;
    for (int e = beg; e < end; e++) {
        float2 cw = g_csr[e];
        int    s  = __float_as_int(cw.x);
        sum = fmaf(cw.y, g_hw1[s * HD + k], sum);
    }
    float val = sum + g_dself[n] * g_hw1[n * HD + k] + bc1[k];
    float tot = gsum64(val, s1, g, tid);
    float mu  = tot * (1.0f / 64.0f);
    float d   = val - mu;
    float vt  = gsum64(d * d, s2, g, tid);
    float var = vt * (1.0f / 64.0f);
    sh[g][k] = fmaxf(d * rsqrtf(var + EPSV) * g1[k] + be1[k], 0.0f);
    __syncthreads();
    float o = 0.f;
#pragma unroll 8
    for (int i = 0; i < HD; i++)
        o = fmaf(sh[g][i], Wc2[i * HD + k], o);
    g_hw2[n * HD + k] = o;
}

// ---------------- K8: agg(hw2)+LN+relu; node_pred = h2@Wout+bout ----------------
__global__ __launch_bounds__(256) void k_agg2(
    const float* __restrict__ bc2, const float* __restrict__ g2,
    const float* __restrict__ be2, const float* __restrict__ Wout,
    const float* __restrict__ bout, float* __restrict__ node_pred) {
    __shared__ float s1[8], s2[8];
    __shared__ float sh[4][HD];
    int tid = threadIdx.x;
    int g = tid >> 6;
    int n = blockIdx.x * 4 + g;
    int k = tid & 63;
    int beg = g_rowptr[n], end = g_rowptr[n + 1];
    float sum = 0.f;
    for (int e = beg; e < end; e++) {
        float2 cw = g_csr[e];
        int    s  = __float_as_int(cw.x);
        sum = fmaf(cw.y, g_hw2[s * HD + k], sum);
    }
    float val = sum + g_dself[n] * g_hw2[n * HD + k] + bc2[k];
    float tot = gsum64(val, s1, g, tid);
    float mu  = tot * (1.0f / 64.0f);
    float d   = val - mu;
    float vt  = gsum64(d * d, s2, g, tid);
    float var = vt * (1.0f / 64.0f);
    sh[g][k] = fmaxf(d * rsqrtf(var + EPSV) * g2[k] + be2[k], 0.0f);
    __syncthreads();
    if (k < OUTD) {
        float o = bout[k];
#pragma unroll 8
        for (int i = 0; i < HD; i++)
            o = fmaf(sh[g][i], Wout[i * OUTD + k], o);
        node_pred[n * OUTD + k] = o;
    }
}

// ---------------- K9: scores with packed f32x2 (R2 proven) ----------------
__device__ __forceinline__ void lds2(unsigned long long& x, unsigned long long& y,
                                     const float* p) {
    unsigned a = (unsigned)__cvta_generic_to_shared(p);
    asm volatile("ld.shared.v2.b64 {%0, %1}, [%2];" : "=l"(x), "=l"(y) : "r"(a));
}

__device__ __forceinline__ void rfma(unsigned long long& acc, unsigned long long a,
                                     unsigned long long b, unsigned long long w) {
    unsigned long long t, m;
    float lo, hi;
    asm("add.rn.f32x2 %0, %1, %2;" : "=l"(t) : "l"(a), "l"(b));
    asm("mov.b64 {%0, %1}, %2;" : "=f"(lo), "=f"(hi) : "l"(t));
    lo = fmaxf(lo, 0.0f);
    hi = fmaxf(hi, 0.0f);
    asm("mov.b64 %0, {%1, %2};" : "=l"(m) : "f"(lo), "f"(hi));
    asm("fma.rn.f32x2 %0, %1, %2, %3;" : "=l"(acc) : "l"(m), "l"(w), "l"(acc));
}

__global__ __launch_bounds__(256) void k_scores(const float* __restrict__ Wi2,
                                                const float* __restrict__ bi2,
                                                float* __restrict__ scores) {
    __shared__ __align__(16) float As[64 * 68];
    __shared__ __align__(16) float Bs[64 * 68];
    __shared__ __align__(16) float Ws[64];
    int tid = threadIdx.x;
    int tx = tid & 15, ty = tid >> 4;
    int i0 = blockIdx.y * 64, j0 = blockIdx.x * 64;

    for (int idx = tid; idx < 4096; idx += 256) {
        int i = idx >> 6, h = idx & 63;
        As[i * 68 + h] = g_A[(i0 + i) * HD + h];
        Bs[i * 68 + h] = g_B[(j0 + i) * HD + h];
    }
    if (tid < 64) Ws[tid] = Wi2[tid];
    __syncthreads();

    unsigned long long acc[4][4];
#pragma unroll
    for (int ii = 0; ii < 4; ii++)
#pragma unroll
        for (int jj = 0; jj < 4; jj++) acc[ii][jj] = 0ull;

    const float* ap = As + ty * 68;
    const float* bp = Bs + tx * 68;
#pragma unroll 2
    for (int h = 0; h < 64; h += 4) {
        unsigned long long a0[4], a1[4], b0[4], b1[4], w0, w1;
        lds2(w0, w1, Ws + h);
#pragma unroll
        for (int ii = 0; ii < 4; ii++)
            lds2(a0[ii], a1[ii], ap + ii * (16 * 68) + h);
#pragma unroll
        for (int jj = 0; jj < 4; jj++)
            lds2(b0[jj], b1[jj], bp + jj * (16 * 68) + h);
#pragma unroll
        for (int ii = 0; ii < 4; ii++)
#pragma unroll
            for (int jj = 0; jj < 4; jj++) {
                rfma(acc[ii][jj], a0[ii], b0[jj], w0);
                rfma(acc[ii][jj], a1[ii], b1[jj], w1);
            }
    }

    float b2 = bi2[0];
#pragma unroll
    for (int ii = 0; ii < 4; ii++) {
#pragma unroll
        for (int jj = 0; jj < 4; jj++) {
            float lo, hi;
            asm("mov.b64 {%0, %1}, %2;" : "=f"(lo), "=f"(hi) : "l"(acc[ii][jj]));
            int i = i0 + ii * 16 + ty;
            int j = j0 + jj * 16 + tx;
            scores[i * NN + j] = lo + hi + b2;
        }
    }
}

// ---------------- launch ----------------
extern "C" void kernel_launch(void* const* d_in, const int* in_sizes, int n_in,
                              void* d_out, int out_size) {
    (void)out_size;
    bool sig = (in_sizes[1] == 2 * EE);
    const float* x  = (const float*)d_in[0];
    const int*   ei = (const int*)(sig ? d_in[1] : d_in[n_in - 1]);
    const float* ew = (const float*)(sig ? d_in[2] : d_in[1]);
    int wo = sig ? 3 : 2;
    const float* Wcz  = (const float*)d_in[wo + 0];
    const float* bcz  = (const float*)d_in[wo + 1];
    const float* Wlz  = (const float*)d_in[wo + 2];
    const float* blz  = (const float*)d_in[wo + 3];
    const float* Wch  = (const float*)d_in[wo + 8];
    const float* bch  = (const float*)d_in[wo + 9];
    const float* Wlh  = (const float*)d_in[wo + 10];
    const float* blh  = (const float*)d_in[wo + 11];
    const float* Wred = (const float*)d_in[wo + 12];
    const float* bred = (const float*)d_in[wo + 13];
    const float* Wc1  = (const float*)d_in[wo + 14];
    const float* bc1  = (const float*)d_in[wo + 15];
    const float* Wc2  = (const float*)d_in[wo + 16];
    const float* bc2  = (const float*)d_in[wo + 17];
    const float* g1   = (const float*)d_in[wo + 18];
    const float* be1  = (const float*)d_in[wo + 19];
    const float* g2   = (const float*)d_in[wo + 20];
    const float* be2  = (const float*)d_in[wo + 21];
    const float* Wout = (const float*)d_in[wo + 22];
    const float* bout = (const float*)d_in[wo + 23];
    const float* Wi1  = (const float*)d_in[wo + 24];
    const float* bi1  = (const float*)d_in[wo + 25];
    const float* Wi2  = (const float*)d_in[wo + 26];
    const float* bi2  = (const float*)d_in[wo + 27];

    float* outp      = (float*)d_out;
    float* node_pred = outp;
    float* scores    = outp + NN * OUTD;

    k_pre<<<10, 256>>>(Wcz, bcz, Wlz, blz, Wch, bch, Wlh, blh);
    k_deg<<<EE / 256, 256>>>(ei, ew);
    k_scan<<<1, 1024>>>();
    k_sc_gx<<<256 + SEQL * NN / 4, 256>>>(ei, ew, x);
    k_aggHT<<<NN / 4, 256>>>();
    k_red_plus<<<NN / 8, 512>>>(Wred, bred, Wc1, Wi1, bi1);
    k_agg1<<<NN / 4, 256>>>(bc1, g1, be1, Wc2);
    k_agg2<<<NN / 4, 256>>>(bc2, g2, be2, Wout, bout, node_pred);
    dim3 sgrid(NN / 64, NN / 64);
    k_scores<<<sgrid, 256>>>(Wi2, bi2, scores);
}